// round 15
// baseline (speedup 1.0000x reference)
#include <cuda_runtime.h>
#include <math.h>

// NeuralstackOnly — parallel decomposition.
// The scan's scalar coefficients are computable in parallel:
//   interp_t = cos(le, x_t)            (independent of latch)  -> K1
//   latch_t  = (1-i_t) latch_{t-1} + i_t x_t   (known coeffs)  -> K2 (reg-resident scan)
//   pop_t    = elu(cos(sp, latch_{t-1}))                       -> K3
//   pointer recurrence (12-wide, tiny, serial)                 -> K4
//   stack_t  = al stack_{t-1} + be x_t + ga ; top = sum np*s   -> K5 (reg-resident scan)
// Heavy passes use the full chip and are memory/FMA bound; no barriers in hot loops.

#define EPSF 1e-8f
#define ZOFF 0.001f
#define NSTK 12
#define MAXBT 16384

__device__ float  g_i[MAXBT];            // interp per (b,t)
__device__ float4 g_coef[MAXBT * NSTK];  // (al, be, ga, np) per (b,t,n)
__device__ float  g_norms[2];            // max(|sp|,eps), max(|le|,eps)

__device__ __forceinline__ float warpsum(float v) {
#pragma unroll
    for (int m = 16; m > 0; m >>= 1) v += __shfl_xor_sync(0xffffffffu, v, m);
    return v;
}

// ---- K0: parameter norms (once) ----
__global__ void k_norms(const float* __restrict__ sp, const float* __restrict__ le, int V) {
    float a = 0.f, b = 0.f;
    for (int j = threadIdx.x; j < V; j += blockDim.x) {
        float s = sp[j], l = le[j];
        a += s * s; b += l * l;
    }
    a = warpsum(a); b = warpsum(b);
    __shared__ float sa[8], sb[8];
    int w = threadIdx.x >> 5, ln = threadIdx.x & 31;
    if (ln == 0) { sa[w] = a; sb[w] = b; }
    __syncthreads();
    if (threadIdx.x == 0) {
        float ta = 0.f, tb = 0.f;
        int nw = blockDim.x >> 5;
        for (int i = 0; i < nw; i++) { ta += sa[i]; tb += sb[i]; }
        g_norms[0] = fmaxf(sqrtf(ta), EPSF);
        g_norms[1] = fmaxf(sqrtf(tb), EPSF);
    }
}

// ---- K1: interp_t = cos(le, x_t) per (b,t) ----
__global__ void k_interp(const float* __restrict__ x, const float* __restrict__ le, int V) {
    int bt = blockIdx.x;
    const float4* row = (const float4*)(x + (size_t)bt * V);
    const float4* lep = (const float4*)le;
    float dl = 0.f, d2 = 0.f;
    for (int j = threadIdx.x; j < (V >> 2); j += blockDim.x) {
        float4 xv = row[j], lv = lep[j];
        dl += xv.x * lv.x + xv.y * lv.y + xv.z * lv.z + xv.w * lv.w;
        d2 += xv.x * xv.x + xv.y * xv.y + xv.z * xv.z + xv.w * xv.w;
    }
    dl = warpsum(dl); d2 = warpsum(d2);
    __shared__ float sa[8], sb[8];
    int w = threadIdx.x >> 5, ln = threadIdx.x & 31;
    if (ln == 0) { sa[w] = dl; sb[w] = d2; }
    __syncthreads();
    if (threadIdx.x == 0) {
        float ta = 0.f, tb = 0.f;
        int nw = blockDim.x >> 5;
        for (int i = 0; i < nw; i++) { ta += sa[i]; tb += sb[i]; }
        float nx = fmaxf(sqrtf(tb), EPSF);
        g_i[bt] = ta / (g_norms[1] * nx);
    }
}

// ---- K2: latch scan over T, state in registers (float2 per thread) ----
__global__ void __launch_bounds__(128) k_latch(const float* __restrict__ x,
                                               const float* __restrict__ l0,
                                               float* __restrict__ latches, int T, int V) {
    int nvt = V >> 8;                          // 256-lane tiles
    int b = blockIdx.x / nvt, vt = blockIdx.x % nvt;
    int v = (vt << 8) + (threadIdx.x << 1);
    float2 lat = *(const float2*)(l0 + (size_t)b * V + v);
    const float* xp = x + (size_t)b * T * V + v;
    float* lp = latches + (size_t)b * T * V + v;
    const float* ip = g_i + b * T;
#pragma unroll 4
    for (int t = 0; t < T; t++) {
        float2 xv = *(const float2*)xp;
        float i = ip[t], oi = 1.f - i;
        lat.x = oi * lat.x + i * xv.x;
        lat.y = oi * lat.y + i * xv.y;
        *(float2*)lp = lat;
        xp += V; lp += V;
    }
}

// ---- K3: pop_t = elu(cos(sp, latch_{t-1})) per (b,t) ----
__global__ void k_pop(const float* __restrict__ latches, const float* __restrict__ l0,
                      const float* __restrict__ sp, float* __restrict__ pops, int T, int V) {
    int bt = blockIdx.x;
    int b = bt / T, t = bt - b * T;
    const float* row = (t == 0) ? (l0 + (size_t)b * V)
                                : (latches + (size_t)(bt - 1) * V);
    const float4* r4 = (const float4*)row;
    const float4* sp4 = (const float4*)sp;
    float ds = 0.f, d2 = 0.f;
    for (int j = threadIdx.x; j < (V >> 2); j += blockDim.x) {
        float4 lv = r4[j], sv = sp4[j];
        ds += lv.x * sv.x + lv.y * sv.y + lv.z * sv.z + lv.w * sv.w;
        d2 += lv.x * lv.x + lv.y * lv.y + lv.z * lv.z + lv.w * lv.w;
    }
    ds = warpsum(ds); d2 = warpsum(d2);
    __shared__ float sa[8], sb[8];
    int w = threadIdx.x >> 5, ln = threadIdx.x & 31;
    if (ln == 0) { sa[w] = ds; sb[w] = d2; }
    __syncthreads();
    if (threadIdx.x == 0) {
        float ta = 0.f, tb = 0.f;
        int nw = blockDim.x >> 5;
        for (int i = 0; i < nw; i++) { ta += sa[i]; tb += sb[i]; }
        float nb = fmaxf(sqrtf(tb), EPSF);
        float cs = ta / (g_norms[0] * nb);
        pops[bt] = (cs > 0.f) ? cs : expm1f(cs);   // jax.nn.elu
    }
}

// ---- K4: pointer recurrence (12-wide), one warp per batch ----
__global__ void k_coef(const float* __restrict__ sharp_ptr, const float* __restrict__ pops, int T) {
    int b = blockIdx.x, lane = threadIdx.x;
    float sharp = sharp_ptr[0];
    bool fast5 = (sharp == 5.0f);
    const float* pq = pops + b * T;
    float4* cp = g_coef + (size_t)b * T * NSTK;
    float pv = (lane == 0) ? 1.f : 0.f;
    for (int t = 0; t < T; t++) {
        float pop = pq[t], push = 1.f - pop;
        float pp = __shfl_sync(0xffffffffu, pv, (lane + 11) % 12);  // ptr_push
        float pr = __shfl_sync(0xffffffffu, pv, (lane + 1) % 12);   // ptr_pop
        float mix = push * pp + pop * pr;
        float m = fmaxf(mix, 0.f);
        float pw;
        if (fast5) { float m2 = m * m; pw = m2 * m2 * m; }
        else       { pw = powf(m, sharp); }
        float pz = (lane < NSTK) ? pw : 0.f;
#pragma unroll
        for (int s = 8; s > 0; s >>= 1) pz += __shfl_xor_sync(0xffffffffu, pz, s);
        float np = pw / (pz + EPSF);
        if (lane < NSTK) {
            float al = push * (1.f - pp) + pop * (1.f - pv);
            float be = push * pp;
            float ga = pop * ZOFF * pv;
            cp[t * NSTK + lane] = make_float4(al, be, ga, np);
        }
        pv = np;
    }
}

// ---- K5: stack scan + top/out, state in registers (float2 x 12 per thread) ----
__global__ void __launch_bounds__(128) k_stack(const float* __restrict__ x,
                                               const float* __restrict__ pops,
                                               float* __restrict__ outs,
                                               float* __restrict__ tops, int T, int V) {
    int nvt = V >> 8;
    int b = blockIdx.x / nvt, vt = blockIdx.x % nvt;
    int v = (vt << 8) + (threadIdx.x << 1);
    float2 s[NSTK];
#pragma unroll
    for (int n = 0; n < NSTK; n++) { s[n].x = ZOFF; s[n].y = ZOFF; }
    const float* xp = x + (size_t)b * T * V + v;
    float* op = outs + (size_t)b * T * V + v;
    float* tp = tops + (size_t)b * T * V + v;
    const float4* cp = g_coef + (size_t)b * T * NSTK;
    const float* pq = pops + b * T;
    for (int t = 0; t < T; t++) {
        float2 xv = *(const float2*)xp;
        float tx = 0.f, ty = 0.f;
#pragma unroll
        for (int n = 0; n < NSTK; n++) {
            float4 c = cp[n];                       // uniform per warp: L1 broadcast
            s[n].x = c.x * s[n].x + (c.y * xv.x + c.z);
            s[n].y = c.x * s[n].y + (c.y * xv.y + c.z);
            tx += c.w * s[n].x;
            ty += c.w * s[n].y;
        }
        float pop = pq[t];
        *(float2*)tp = make_float2(tx, ty);
        *(float2*)op = make_float2(pop * tx, pop * ty);
        cp += NSTK; xp += V; op += V; tp += V;
    }
}

extern "C" void kernel_launch(void* const* d_in, const int* in_sizes, int n_in,
                              void* d_out, int out_size)
{
    const float* x     = (const float*)d_in[0];   // [B,T,V]
    const float* sp    = (const float*)d_in[1];   // [V]
    const float* sharp = (const float*)d_in[2];   // [1]
    const float* le    = (const float*)d_in[3];   // [V]
    const float* l0    = (const float*)d_in[4];   // [B,V]

    const int V = in_sizes[1];
    const int B = in_sizes[4] / V;
    const int T = in_sizes[0] / (B * V);
    (void)n_in; (void)out_size;

    float* out = (float*)d_out;
    const size_t BTV = (size_t)B * T * V;
    float* outs    = out;                               // [B,T,V]
    float* latches = out + BTV;                         // [B,T,V]
    float* pops    = out + 2 * BTV;                     // [B,T]
    float* tops    = out + 2 * BTV + (size_t)B * T;     // [B,T,V]

    const int nvt = V >> 8;                             // 256-lane tiles

    k_norms <<<1,        256>>>(sp, le, V);
    k_interp<<<B * T,    256>>>(x, le, V);
    k_latch <<<B * nvt,  128>>>(x, l0, latches, T, V);
    k_pop   <<<B * T,    256>>>(latches, l0, sp, pops, T, V);
    k_coef  <<<B,         32>>>(sharp, pops, T);
    k_stack <<<B * nvt,  128>>>(x, pops, outs, tops, T, V);
}